// round 9
// baseline (speedup 1.0000x reference)
#include <cuda_runtime.h>
#include <cuda_fp16.h>
#include <cstdint>

#define D        64
#define MT       64          // x rows per CTA (16 per warp)
#define NC       64          // codes per chunk
#define TPB      128
#define MAXM     4096
#define NR       3           // B ring depth (chunks)

__device__ __align__(16) __half g_codes_f16[MAXM * D];
__device__ __align__(16) __half g_c2h[MAXM];          // fp16(-||c||^2 / 2)

static __device__ __forceinline__ uint32_t su32(const void* p) {
    uint32_t a;
    asm("{ .reg .u64 t; cvta.to.shared.u64 t, %1; cvt.u32.u64 %0, t; }" : "=r"(a) : "l"(p));
    return a;
}
static __device__ __forceinline__ uint32_t h2u(__half2 h) {
    return *reinterpret_cast<uint32_t*>(&h);
}
static __device__ __forceinline__ __half2 u2h(uint32_t u) {
    return *reinterpret_cast<__half2*>(&u);
}

#define LDSM4(r0, r1, r2, r3, addr)                                                   \
    asm volatile("ldmatrix.sync.aligned.m8n8.x4.shared.b16 {%0,%1,%2,%3}, [%4];"      \
                 : "=r"(r0), "=r"(r1), "=r"(r2), "=r"(r3) : "r"(addr))

#define MMA16816H(c0, c1, a, b0, b1)                                                  \
    asm volatile("mma.sync.aligned.m16n8k16.row.col.f16.f16.f16.f16 "                 \
                 "{%0,%1},{%2,%3,%4,%5},{%6,%7},{%0,%1};"                             \
                 : "+r"(c0), "+r"(c1)                                                 \
                 : "r"((a)[0]), "r"((a)[1]), "r"((a)[2]), "r"((a)[3]),                \
                   "r"(b0), "r"(b1))

#define CPASYNC16(saddr, gptr)                                                        \
    asm volatile("cp.async.cg.shared.global [%0], [%1], 16;" :: "r"(saddr), "l"(gptr))
#define CPCOMMIT() asm volatile("cp.async.commit_group;")
#define CPWAIT(n)  asm volatile("cp.async.wait_group %0;" :: "n"(n))

// ---------------- prep: 16 threads per code row ----------------
__global__ void prep_kernel(const float* __restrict__ codes, int M) {
    int gid = blockIdx.x * blockDim.x + threadIdx.x;
    int m = gid >> 4, seg = gid & 15;
    if (m >= M) return;
    float4 v = __ldg(reinterpret_cast<const float4*>(codes + (size_t)m * D) + seg);
    float s = v.x * v.x + v.y * v.y + v.z * v.z + v.w * v.w;
    s += __shfl_xor_sync(0xFFFFFFFFu, s, 1);
    s += __shfl_xor_sync(0xFFFFFFFFu, s, 2);
    s += __shfl_xor_sync(0xFFFFFFFFu, s, 4);
    s += __shfl_xor_sync(0xFFFFFFFFu, s, 8);
    uint2 u;
    u.x = h2u(__floats2half2_rn(v.x, v.y));
    u.y = h2u(__floats2half2_rn(v.z, v.w));
    reinterpret_cast<uint2*>(g_codes_f16 + (size_t)m * D)[seg] = u;
    if (seg == 0) g_c2h[m] = __float2half_rn(-0.5f * s);   // acc-init form
}

// ---------------- phase 1: max(dot - c^2/2) per row ----------------
__global__ __launch_bounds__(TPB, 6) void nn_mma_kernel(
    const float* __restrict__ x, float* __restrict__ out, int M)
{
    __shared__ __align__(128) unsigned char sA[MT * 128];        // 8 KB
    __shared__ __align__(128) unsigned char sB[NR][NC * 128];    // 24 KB
    __shared__ float sx2[MT];

    const int t = threadIdx.x;
    const int L = t & 31;
    const int w = t >> 5;
    const int CHUNKS = M / NC;          // 64

    // ---- stage x rows (threads 0-63 own one row each) ----
    if (t < MT) {
        const float4* xr = reinterpret_cast<const float4*>(
            x + ((size_t)blockIdx.x * MT + t) * D);
        float x2 = 0.f;
#pragma unroll
        for (int i = 0; i < 8; i++) {
            float4 f0 = xr[2 * i], f1 = xr[2 * i + 1];
            x2 += f0.x * f0.x + f0.y * f0.y + f0.z * f0.z + f0.w * f0.w;
            x2 += f1.x * f1.x + f1.y * f1.y + f1.z * f1.z + f1.w * f1.w;
            uint4 u;
            u.x = h2u(__floats2half2_rn(f0.x, f0.y));
            u.y = h2u(__floats2half2_rn(f0.z, f0.w));
            u.z = h2u(__floats2half2_rn(f1.x, f1.y));
            u.w = h2u(__floats2half2_rn(f1.z, f1.w));
            *reinterpret_cast<uint4*>(sA + t * 128 + ((i ^ (t & 7)) << 4)) = u;
        }
        sx2[t] = x2;
    }

    const uint32_t sAb = su32(sA);
    uint32_t sBb[NR];
#pragma unroll
    for (int s = 0; s < NR; s++) sBb[s] = su32(sB[s]);

    auto prefetch = [&](int ch) {
        const uint32_t dst = sBb[ch % NR];
        const char* src = reinterpret_cast<const char*>(g_codes_f16)
                          + (size_t)ch * NC * D * 2;
#pragma unroll
        for (int i = 0; i < 4; i++) {
            int idx = t + i * TPB;
            int n = idx >> 3, kb = idx & 7;
            CPASYNC16(dst + n * 128 + ((kb ^ (n & 7)) << 4), src + idx * 16);
        }
        CPCOMMIT();
    };

    prefetch(0);
    prefetch(1);
    __syncthreads();            // sA + sx2 visible

    // ---- A fragments: warp w owns rows w*16 .. w*16+15 ----
    uint32_t Af[4][4];
    const int mbw = w * 16;
#pragma unroll
    for (int k = 0; k < 4; k++) {
        int r  = mbw + (L & 15);
        int kb = 2 * k + (L >> 4);
        uint32_t addr = sAb + r * 128 + ((kb ^ (r & 7)) << 4);
        LDSM4(Af[k][0], Af[k][1], Af[k][2], Af[k][3], addr);
    }

    const int g   = L >> 2;
    const int tc  = L & 3;
    const int rrb = (L & 7) + ((L >> 4) << 3);
    const int kbb = (L >> 3) & 1;

    __half2 kmax[2];            // [row-half]
    kmax[0] = __floats2half2_rn(-65504.f, -65504.f);
    kmax[1] = kmax[0];

    for (int ch = 0; ch < CHUNKS; ch++) {
        if (ch >= CHUNKS - 1) { CPWAIT(0); } else { CPWAIT(1); }
        __syncthreads();        // chunk ch published; slot (ch+2)%NR free to refill
        if (ch + 2 < CHUNKS) prefetch(ch + 2);

        const uint32_t sBc = sBb[ch % NR];
        const int cb = ch * NC;

#pragma unroll
        for (int p = 0; p < 4; p++) {
            uint32_t c20 = __ldg(reinterpret_cast<const uint32_t*>(g_c2h + cb + (2 * p) * 8 + tc * 2));
            uint32_t c21 = __ldg(reinterpret_cast<const uint32_t*>(g_c2h + cb + (2 * p + 1) * 8 + tc * 2));

            uint32_t a00 = c20, a01 = c20;   // ntile 2p   (two row-halves)
            uint32_t a10 = c21, a11 = c21;   // ntile 2p+1

            const int rr = p * 16 + rrb;
#pragma unroll
            for (int k = 0; k < 4; k++) {
                const int kb = 2 * k + kbb;
                uint32_t b0, b1, b2, b3;
                LDSM4(b0, b1, b2, b3, sBc + rr * 128 + ((kb ^ (rr & 7)) << 4));
                MMA16816H(a00, a01, Af[k], b0, b1);
                MMA16816H(a10, a11, Af[k], b2, b3);
            }
            kmax[0] = __hmax2(kmax[0], __hmax2(u2h(a00), u2h(a10)));
            kmax[1] = __hmax2(kmax[1], __hmax2(u2h(a01), u2h(a11)));
        }
    }

    // ---- reduce across 4 tc lanes; min d^2 = x^2 - 2*max ----
#pragma unroll
    for (int h = 0; h < 2; h++) {
        uint32_t k = h2u(kmax[h]);
        k = h2u(__hmax2(u2h(k), u2h(__shfl_xor_sync(0xFFFFFFFFu, k, 1))));
        k = h2u(__hmax2(u2h(k), u2h(__shfl_xor_sync(0xFFFFFFFFu, k, 2))));
        if (tc == 0) {
            __half2 v = u2h(k);
            float smax = fmaxf(__half2float(__low2half(v)), __half2float(__high2half(v)));
            int row = mbw + h * 8 + g;
            out[(size_t)blockIdx.x * MT + row] = fmaf(smax, -2.f, sx2[row]);  // approx min d^2
        }
    }
}

// ---------------- phase 2: threshold / (rare) exact rescan ----------------
__global__ void finalize_kernel(const float* __restrict__ x,
                                const float* __restrict__ codes,
                                float* __restrict__ out, int M)
{
    int row = blockIdx.x * blockDim.x + threadIdx.x;
    float d2a = out[row];
    if (d2a > 4.0f) {            // fp16 error << 3.9; true d2 certainly > 0.1
        out[row] = -1.0f;
        return;
    }
    const float* xr = x + (size_t)row * D;
    float xv[D];
#pragma unroll
    for (int i = 0; i < D; i++) xv[i] = __ldg(xr + i);
    float best = 3.4e38f;
    int   bi = 0;
    for (int m = 0; m < M; m++) {
        const float* c = codes + (size_t)m * D;
        float s = 0.f;
#pragma unroll
        for (int i = 0; i < D; i++) {
            float dd = xv[i] - __ldg(c + i);
            s += dd * dd;
        }
        if (s < best) { best = s; bi = m; }
    }
    out[row] = (best <= 0.1f) ? (float)bi : -1.0f;
}

extern "C" void kernel_launch(void* const* d_in, const int* in_sizes, int n_in,
                              void* d_out, int out_size) {
    const float* x     = (const float*)d_in[0];
    const float* codes = (const float*)d_in[1];
    float*       out   = (float*)d_out;

    const int M     = in_sizes[1] / D;     // 4096
    const int nRows = in_sizes[0] / D;     // 65536

    prep_kernel<<<(M * 16) / 256, 256>>>(codes, M);
    nn_mma_kernel<<<nRows / MT, TPB>>>(x, out, M);
    finalize_kernel<<<nRows / 256, 256>>>(x, codes, out, M);
}

// round 10
// speedup vs baseline: 1.0855x; 1.0855x over previous
#include <cuda_runtime.h>
#include <cuda_fp16.h>
#include <cstdint>

#define D        64
#define MT       128         // x rows per CTA
#define NC       64          // codes per chunk
#define TPB      256         // 8 warps: 2 code-groups of 4
#define MAXM     4096

__device__ __align__(16) __half g_codes_f16[MAXM * D];
__device__ __align__(16) __half g_c2h[MAXM];          // fp16(-||c||^2 / 2)

static __device__ __forceinline__ uint32_t su32(const void* p) {
    uint32_t a;
    asm("{ .reg .u64 t; cvta.to.shared.u64 t, %1; cvt.u32.u64 %0, t; }" : "=r"(a) : "l"(p));
    return a;
}
static __device__ __forceinline__ uint32_t h2u(__half2 h) {
    return *reinterpret_cast<uint32_t*>(&h);
}
static __device__ __forceinline__ __half2 u2h(uint32_t u) {
    return *reinterpret_cast<__half2*>(&u);
}

#define LDSM4(r0, r1, r2, r3, addr)                                                   \
    asm volatile("ldmatrix.sync.aligned.m8n8.x4.shared.b16 {%0,%1,%2,%3}, [%4];"      \
                 : "=r"(r0), "=r"(r1), "=r"(r2), "=r"(r3) : "r"(addr))

#define MMA16816H(c0, c1, a, b0, b1)                                                  \
    asm volatile("mma.sync.aligned.m16n8k16.row.col.f16.f16.f16.f16 "                 \
                 "{%0,%1},{%2,%3,%4,%5},{%6,%7},{%0,%1};"                             \
                 : "+r"(c0), "+r"(c1)                                                 \
                 : "r"((a)[0]), "r"((a)[1]), "r"((a)[2]), "r"((a)[3]),                \
                   "r"(b0), "r"(b1))

#define CPASYNC16(saddr, gptr)                                                        \
    asm volatile("cp.async.cg.shared.global [%0], [%1], 16;" :: "r"(saddr), "l"(gptr))
#define CPCOMMIT() asm volatile("cp.async.commit_group;")
#define CPWAIT(n)  asm volatile("cp.async.wait_group %0;" :: "n"(n))

// ---------------- prep: 16 threads per code row ----------------
__global__ void prep_kernel(const float* __restrict__ codes, int M) {
    int gid = blockIdx.x * blockDim.x + threadIdx.x;
    int m = gid >> 4, seg = gid & 15;
    if (m >= M) return;
    float4 v = __ldg(reinterpret_cast<const float4*>(codes + (size_t)m * D) + seg);
    float s = v.x * v.x + v.y * v.y + v.z * v.z + v.w * v.w;
    s += __shfl_xor_sync(0xFFFFFFFFu, s, 1);
    s += __shfl_xor_sync(0xFFFFFFFFu, s, 2);
    s += __shfl_xor_sync(0xFFFFFFFFu, s, 4);
    s += __shfl_xor_sync(0xFFFFFFFFu, s, 8);
    uint2 u;
    u.x = h2u(__floats2half2_rn(v.x, v.y));
    u.y = h2u(__floats2half2_rn(v.z, v.w));
    reinterpret_cast<uint2*>(g_codes_f16 + (size_t)m * D)[seg] = u;
    if (seg == 0) g_c2h[m] = __float2half_rn(-0.5f * s);   // acc-init form
}

// smem layout (dynamic, 50688 B):
//  [0,48K):     6 B-slots of 8KB; group0 ring = slots 0-2, group1 ring = slots 3-5.
//               A is staged transiently in slots 4-5 and consumed before g1 uses them.
//  [48K, +512): sx2 (128 floats)
//  [48.5K,+1K): sMin (2 x 128 floats)
#define SMEM_TOTAL (48*1024 + 512 + 1024)

__global__ void __launch_bounds__(TPB, 4) nn_mma_kernel(
    const float* __restrict__ x, float* __restrict__ out, int M)
{
    extern __shared__ __align__(128) unsigned char sm[];
    float* sx2  = reinterpret_cast<float*>(sm + 48 * 1024);
    float* sMin = reinterpret_cast<float*>(sm + 48 * 1024 + 512);

    const int t   = threadIdx.x;
    const int L   = t & 31;
    const int w   = t >> 5;
    const int grp = w >> 2;        // code-group: 0 or 1
    const int wg  = w & 3;         // warp within group (row set)
    const int tg  = t & 127;
    const int LCH = (M / NC) / 2;  // 32 chunks per group

    // ---- stage x rows into slots 4-5 (threads 0-127, one row each) ----
    if (t < MT) {
        const float4* xr = reinterpret_cast<const float4*>(
            x + ((size_t)blockIdx.x * MT + t) * D);
        unsigned char* sA = sm + 4 * 8192;
        float x2 = 0.f;
#pragma unroll
        for (int i = 0; i < 8; i++) {
            float4 f0 = xr[2 * i], f1 = xr[2 * i + 1];
            x2 += f0.x * f0.x + f0.y * f0.y + f0.z * f0.z + f0.w * f0.w;
            x2 += f1.x * f1.x + f1.y * f1.y + f1.z * f1.z + f1.w * f1.w;
            uint4 u;
            u.x = h2u(__floats2half2_rn(f0.x, f0.y));
            u.y = h2u(__floats2half2_rn(f0.z, f0.w));
            u.z = h2u(__floats2half2_rn(f1.x, f1.y));
            u.w = h2u(__floats2half2_rn(f1.z, f1.w));
            *reinterpret_cast<uint4*>(sA + t * 128 + ((i ^ (t & 7)) << 4)) = u;
        }
        sx2[t] = x2;
    }

    const uint32_t sBb = su32(sm);

    // prefetch group-local chunk lc into slot grp*3 + lc%3 (8KB, 128 threads/group)
    auto prefetch = [&](int lc) {
        const uint32_t dst = sBb + (uint32_t)(grp * 3 + (lc % 3)) * 8192u;
        const char* src = reinterpret_cast<const char*>(g_codes_f16)
                          + (size_t)(grp * LCH + lc) * NC * D * 2;
#pragma unroll
        for (int i = 0; i < 4; i++) {
            int idx = tg + i * 128;
            int n = idx >> 3, kb = idx & 7;
            CPASYNC16(dst + n * 128 + ((kb ^ (n & 7)) << 4), src + idx * 16);
        }
        CPCOMMIT();
    };

    __syncthreads();             // A + sx2 staged

    // g0 may start both prefetches now (slots 0,1); g1 only slot 3 (slots 4,5 hold A)
    prefetch(0);
    if (grp == 0) prefetch(1);

    // ---- A fragments (registers for whole kernel): warp owns rows wg*32..wg*32+31 ----
    uint32_t Af[2][4][4];
    const uint32_t sAb = sBb + 4 * 8192;
    const int mbw = wg * 32;
#pragma unroll
    for (int mt = 0; mt < 2; mt++)
#pragma unroll
        for (int k = 0; k < 4; k++) {
            int r  = mbw + mt * 16 + (L & 15);
            int kb = 2 * k + (L >> 4);
            uint32_t addr = sAb + r * 128 + ((kb ^ (r & 7)) << 4);
            LDSM4(Af[mt][k][0], Af[mt][k][1], Af[mt][k][2], Af[mt][k][3], addr);
        }

    __syncthreads();             // A fully consumed -> slots 4,5 free for g1
    if (grp == 1) prefetch(1);   // both groups now have 2 commits outstanding

    const int g   = L >> 2;
    const int tc  = L & 3;
    const int rrb = (L & 7) + ((L >> 4) << 3);
    const int kbb = (L >> 3) & 1;

    __half2 kmax[2][2];
#pragma unroll
    for (int a = 0; a < 2; a++)
#pragma unroll
        for (int b = 0; b < 2; b++) kmax[a][b] = __floats2half2_rn(-65504.f, -65504.f);

    for (int lc = 0; lc < LCH; lc++) {
        if (lc >= LCH - 1) { CPWAIT(0); } else { CPWAIT(1); }   // chunk lc landed
        __syncthreads();         // slot (lc-1)%3 consumers done; chunk lc published
        if (lc + 2 < LCH) prefetch(lc + 2);

        const uint32_t sBc = sBb + (uint32_t)(grp * 3 + (lc % 3)) * 8192u;
        const int cb = (grp * LCH + lc) * NC;

#pragma unroll
        for (int p = 0; p < 4; p++) {
            uint32_t c20 = __ldg(reinterpret_cast<const uint32_t*>(g_c2h + cb + (2 * p) * 8 + tc * 2));
            uint32_t c21 = __ldg(reinterpret_cast<const uint32_t*>(g_c2h + cb + (2 * p + 1) * 8 + tc * 2));

            uint32_t a000 = c20, a001 = c20, a010 = c21, a011 = c21;   // m-tile 0
            uint32_t a100 = c20, a101 = c20, a110 = c21, a111 = c21;   // m-tile 1

            const int rr = p * 16 + rrb;
#pragma unroll
            for (int k = 0; k < 4; k++) {
                const int kb = 2 * k + kbb;
                uint32_t b0, b1, b2, b3;
                LDSM4(b0, b1, b2, b3, sBc + rr * 128 + ((kb ^ (rr & 7)) << 4));
                MMA16816H(a000, a001, Af[0][k], b0, b1);
                MMA16816H(a010, a011, Af[0][k], b2, b3);
                MMA16816H(a100, a101, Af[1][k], b0, b1);
                MMA16816H(a110, a111, Af[1][k], b2, b3);
            }
            kmax[0][0] = __hmax2(kmax[0][0], __hmax2(u2h(a000), u2h(a010)));
            kmax[0][1] = __hmax2(kmax[0][1], __hmax2(u2h(a001), u2h(a011)));
            kmax[1][0] = __hmax2(kmax[1][0], __hmax2(u2h(a100), u2h(a110)));
            kmax[1][1] = __hmax2(kmax[1][1], __hmax2(u2h(a101), u2h(a111)));
        }
    }

    // ---- per-group reduce across tc lanes, publish per-row min d^2 ----
#pragma unroll
    for (int mt = 0; mt < 2; mt++)
#pragma unroll
        for (int h = 0; h < 2; h++) {
            uint32_t k = h2u(kmax[mt][h]);
            k = h2u(__hmax2(u2h(k), u2h(__shfl_xor_sync(0xFFFFFFFFu, k, 1))));
            k = h2u(__hmax2(u2h(k), u2h(__shfl_xor_sync(0xFFFFFFFFu, k, 2))));
            if (tc == 0) {
                __half2 v = u2h(k);
                float smax = fmaxf(__half2float(__low2half(v)), __half2float(__high2half(v)));
                int row = mbw + mt * 16 + h * 8 + g;
                sMin[grp * 128 + row] = fmaf(smax, -2.f, sx2[row]);
            }
        }

    __syncthreads();
    if (t < MT)
        out[(size_t)blockIdx.x * MT + t] = fminf(sMin[t], sMin[128 + t]);
}

// ---------------- phase 2: threshold / (rare) exact rescan ----------------
__global__ void finalize_kernel(const float* __restrict__ x,
                                const float* __restrict__ codes,
                                float* __restrict__ out, int M)
{
    int row = blockIdx.x * blockDim.x + threadIdx.x;
    float d2a = out[row];
    if (d2a > 4.0f) {            // fp16 error << 3.9; true d2 certainly > 0.1
        out[row] = -1.0f;
        return;
    }
    const float* xr = x + (size_t)row * D;
    float xv[D];
#pragma unroll
    for (int i = 0; i < D; i++) xv[i] = __ldg(xr + i);
    float best = 3.4e38f;
    int   bi = 0;
    for (int m = 0; m < M; m++) {
        const float* c = codes + (size_t)m * D;
        float s = 0.f;
#pragma unroll
        for (int i = 0; i < D; i++) {
            float dd = xv[i] - __ldg(c + i);
            s += dd * dd;
        }
        if (s < best) { best = s; bi = m; }
    }
    out[row] = (best <= 0.1f) ? (float)bi : -1.0f;
}

extern "C" void kernel_launch(void* const* d_in, const int* in_sizes, int n_in,
                              void* d_out, int out_size) {
    const float* x     = (const float*)d_in[0];
    const float* codes = (const float*)d_in[1];
    float*       out   = (float*)d_out;

    const int M     = in_sizes[1] / D;     // 4096
    const int nRows = in_sizes[0] / D;     // 65536

    cudaFuncSetAttribute(nn_mma_kernel,
                         cudaFuncAttributeMaxDynamicSharedMemorySize, SMEM_TOTAL);

    prep_kernel<<<(M * 16) / 256, 256>>>(codes, M);
    nn_mma_kernel<<<nRows / MT, TPB, SMEM_TOTAL>>>(x, out, M);
    finalize_kernel<<<nRows / 256, 256>>>(x, codes, out, M);
}

// round 11
// speedup vs baseline: 1.3157x; 1.2120x over previous
#include <cuda_runtime.h>
#include <cuda_fp16.h>
#include <cstdint>

#define D        64
#define MT       128         // x rows per CTA
#define NC       64          // codes per chunk
#define TPB      128
#define MAXM     4096

__device__ __align__(16) __half g_codes_f16[MAXM * D];
__device__ __align__(16) __half g_c2h[MAXM];          // fp16(-||c||^2 / 2)

static __device__ __forceinline__ uint32_t su32(const void* p) {
    uint32_t a;
    asm("{ .reg .u64 t; cvta.to.shared.u64 t, %1; cvt.u32.u64 %0, t; }" : "=r"(a) : "l"(p));
    return a;
}
static __device__ __forceinline__ uint32_t h2u(__half2 h) {
    return *reinterpret_cast<uint32_t*>(&h);
}
static __device__ __forceinline__ __half2 u2h(uint32_t u) {
    return *reinterpret_cast<__half2*>(&u);
}

#define LDSM4(r0, r1, r2, r3, addr)                                                   \
    asm volatile("ldmatrix.sync.aligned.m8n8.x4.shared.b16 {%0,%1,%2,%3}, [%4];"      \
                 : "=r"(r0), "=r"(r1), "=r"(r2), "=r"(r3) : "r"(addr))

#define MMA16816H(c0, c1, a, b0, b1)                                                  \
    asm volatile("mma.sync.aligned.m16n8k16.row.col.f16.f16.f16.f16 "                 \
                 "{%0,%1},{%2,%3,%4,%5},{%6,%7},{%0,%1};"                             \
                 : "+r"(c0), "+r"(c1)                                                 \
                 : "r"((a)[0]), "r"((a)[1]), "r"((a)[2]), "r"((a)[3]),                \
                   "r"(b0), "r"(b1))

#define CPASYNC16(saddr, gptr)                                                        \
    asm volatile("cp.async.cg.shared.global [%0], [%1], 16;" :: "r"(saddr), "l"(gptr))
#define CPCOMMIT() asm volatile("cp.async.commit_group;")
#define CPWAIT(n)  asm volatile("cp.async.wait_group %0;" :: "n"(n))

// ---------------- prep: 16 threads per code row ----------------
__global__ void prep_kernel(const float* __restrict__ codes, int M) {
    int gid = blockIdx.x * blockDim.x + threadIdx.x;
    int m = gid >> 4, seg = gid & 15;
    if (m >= M) return;
    float4 v = __ldg(reinterpret_cast<const float4*>(codes + (size_t)m * D) + seg);
    float s = v.x * v.x + v.y * v.y + v.z * v.z + v.w * v.w;
    s += __shfl_xor_sync(0xFFFFFFFFu, s, 1);
    s += __shfl_xor_sync(0xFFFFFFFFu, s, 2);
    s += __shfl_xor_sync(0xFFFFFFFFu, s, 4);
    s += __shfl_xor_sync(0xFFFFFFFFu, s, 8);
    uint2 u;
    u.x = h2u(__floats2half2_rn(v.x, v.y));
    u.y = h2u(__floats2half2_rn(v.z, v.w));
    reinterpret_cast<uint2*>(g_codes_f16 + (size_t)m * D)[seg] = u;
    if (seg == 0) g_c2h[m] = __float2half_rn(-0.5f * s);   // acc-init form
}

// ---------------- main: max(dot - c^2/2) per row + fused finalize ----------------
__global__ __launch_bounds__(TPB, 4) void nn_mma_kernel(
    const float* __restrict__ x, const float* __restrict__ codes,
    float* __restrict__ out, int M)
{
    // 48KB: 6 B-chunk slots of 8KB; slots 4,5 double as the transient A staging area
    __shared__ __align__(128) unsigned char sm[6 * NC * 128];
    __shared__ float sD2[MT];

    const int t = threadIdx.x;
    const int L = t & 31;
    const int w = t >> 5;
    const int NPAIR = (M / NC) / 2;     // 32

    // ---- stage x row t into A area (slots 4-5); x2 in a register ----
    float x2 = 0.f;
    {
        const float4* xr = reinterpret_cast<const float4*>(
            x + ((size_t)blockIdx.x * MT + t) * D);
        unsigned char* sA = sm + 4 * NC * 128;
#pragma unroll
        for (int i = 0; i < 8; i++) {
            float4 f0 = xr[2 * i], f1 = xr[2 * i + 1];
            x2 += f0.x * f0.x + f0.y * f0.y + f0.z * f0.z + f0.w * f0.w;
            x2 += f1.x * f1.x + f1.y * f1.y + f1.z * f1.z + f1.w * f1.w;
            uint4 u;
            u.x = h2u(__floats2half2_rn(f0.x, f0.y));
            u.y = h2u(__floats2half2_rn(f0.z, f0.w));
            u.z = h2u(__floats2half2_rn(f1.x, f1.y));
            u.w = h2u(__floats2half2_rn(f1.z, f1.w));
            *reinterpret_cast<uint4*>(sA + t * 128 + ((i ^ (t & 7)) << 4)) = u;
        }
    }

    uint32_t sC[6];
#pragma unroll
    for (int s = 0; s < 6; s++) sC[s] = su32(sm + s * NC * 128);

    // prefetch a PAIR of chunks (16 KB) into ring slot q%3
    auto prefetch_pair = [&](int q) {
        const int slot = (q % 3) * 2;
        const char* src = reinterpret_cast<const char*>(g_codes_f16)
                          + (size_t)q * 2 * NC * D * 2;
#pragma unroll
        for (int c = 0; c < 2; c++) {
            const uint32_t dst = sC[slot + c];
            const char* s2 = src + (size_t)c * NC * D * 2;
#pragma unroll
            for (int i = 0; i < 4; i++) {
                int idx = t + i * TPB;
                int n = idx >> 3, kb = idx & 7;
                CPASYNC16(dst + n * 128 + ((kb ^ (n & 7)) << 4), s2 + idx * 16);
            }
        }
        CPCOMMIT();
    };

    prefetch_pair(0);          // slot 0 (chunks 0,1)
    prefetch_pair(1);          // slot 1 (chunks 2,3)
    __syncthreads();           // A staging visible

    // ---- A fragments from slots 4-5 (registers for whole kernel) ----
    uint32_t Af[2][4][4];
    const uint32_t sAb = sC[4];
    const int mbw = w * 32;
#pragma unroll
    for (int mt = 0; mt < 2; mt++)
#pragma unroll
        for (int k = 0; k < 4; k++) {
            int r  = mbw + mt * 16 + (L & 15);
            int kb = 2 * k + (L >> 4);
            uint32_t addr = sAb + r * 128 + ((kb ^ (r & 7)) << 4);
            LDSM4(Af[mt][k][0], Af[mt][k][1], Af[mt][k][2], Af[mt][k][3], addr);
        }

    const int g   = L >> 2;
    const int tc  = L & 3;
    const int rrb = (L & 7) + ((L >> 4) << 3);
    const int kbb = (L >> 3) & 1;

    __half2 kmax[2][2];
#pragma unroll
    for (int a = 0; a < 2; a++)
#pragma unroll
        for (int b = 0; b < 2; b++) kmax[a][b] = __floats2half2_rn(-65504.f, -65504.f);

    for (int q = 0; q < NPAIR; q++) {
        if (q >= NPAIR - 1) { CPWAIT(0); } else { CPWAIT(1); }   // pair q landed
        __syncthreads();        // all warps done with the slot pair (q+2) will overwrite
        if (q + 2 < NPAIR) prefetch_pair(q + 2);

        const int slot = (q % 3) * 2;
        const uint32_t sB0 = sC[slot];
        const uint32_t sB1 = sC[slot + 1];
        const int cb0 = (2 * q) * NC;
        const int cb1 = (2 * q + 1) * NC;

#pragma unroll
        for (int p = 0; p < 4; p++) {
            uint32_t c2a0 = __ldg(reinterpret_cast<const uint32_t*>(g_c2h + cb0 + (2 * p) * 8 + tc * 2));
            uint32_t c2a1 = __ldg(reinterpret_cast<const uint32_t*>(g_c2h + cb0 + (2 * p + 1) * 8 + tc * 2));
            uint32_t c2b0 = __ldg(reinterpret_cast<const uint32_t*>(g_c2h + cb1 + (2 * p) * 8 + tc * 2));
            uint32_t c2b1 = __ldg(reinterpret_cast<const uint32_t*>(g_c2h + cb1 + (2 * p + 1) * 8 + tc * 2));

            uint32_t acc0[2][2][2], acc1[2][2][2];
#pragma unroll
            for (int mt = 0; mt < 2; mt++) {
                acc0[mt][0][0] = c2a0; acc0[mt][0][1] = c2a0;
                acc0[mt][1][0] = c2a1; acc0[mt][1][1] = c2a1;
                acc1[mt][0][0] = c2b0; acc1[mt][0][1] = c2b0;
                acc1[mt][1][0] = c2b1; acc1[mt][1][1] = c2b1;
            }

            const int rr = p * 16 + rrb;
            uint32_t f[2][8];
            {
                const uint32_t o0 = rr * 128 + ((kbb ^ (rr & 7)) << 4);
                LDSM4(f[0][0], f[0][1], f[0][2], f[0][3], sB0 + o0);
                LDSM4(f[0][4], f[0][5], f[0][6], f[0][7], sB1 + o0);
            }
#pragma unroll
            for (int k = 0; k < 4; k++) {
                if (k < 3) {
                    const uint32_t on = rr * 128 + (((2 * (k + 1) + kbb) ^ (rr & 7)) << 4);
                    LDSM4(f[(k + 1) & 1][0], f[(k + 1) & 1][1], f[(k + 1) & 1][2], f[(k + 1) & 1][3], sB0 + on);
                    LDSM4(f[(k + 1) & 1][4], f[(k + 1) & 1][5], f[(k + 1) & 1][6], f[(k + 1) & 1][7], sB1 + on);
                }
                const uint32_t* b = f[k & 1];
                MMA16816H(acc0[0][0][0], acc0[0][0][1], Af[0][k], b[0], b[1]);
                MMA16816H(acc0[0][1][0], acc0[0][1][1], Af[0][k], b[2], b[3]);
                MMA16816H(acc0[1][0][0], acc0[1][0][1], Af[1][k], b[0], b[1]);
                MMA16816H(acc0[1][1][0], acc0[1][1][1], Af[1][k], b[2], b[3]);
                MMA16816H(acc1[0][0][0], acc1[0][0][1], Af[0][k], b[4], b[5]);
                MMA16816H(acc1[0][1][0], acc1[0][1][1], Af[0][k], b[6], b[7]);
                MMA16816H(acc1[1][0][0], acc1[1][0][1], Af[1][k], b[4], b[5]);
                MMA16816H(acc1[1][1][0], acc1[1][1][1], Af[1][k], b[6], b[7]);
            }

#pragma unroll
            for (int mt = 0; mt < 2; mt++) {
                kmax[mt][0] = __hmax2(kmax[mt][0], u2h(acc0[mt][0][0]));
                kmax[mt][1] = __hmax2(kmax[mt][1], u2h(acc0[mt][0][1]));
                kmax[mt][0] = __hmax2(kmax[mt][0], u2h(acc0[mt][1][0]));
                kmax[mt][1] = __hmax2(kmax[mt][1], u2h(acc0[mt][1][1]));
                kmax[mt][0] = __hmax2(kmax[mt][0], u2h(acc1[mt][0][0]));
                kmax[mt][1] = __hmax2(kmax[mt][1], u2h(acc1[mt][0][1]));
                kmax[mt][0] = __hmax2(kmax[mt][0], u2h(acc1[mt][1][0]));
                kmax[mt][1] = __hmax2(kmax[mt][1], u2h(acc1[mt][1][1]));
            }
        }
    }

    // ---- reduce across 4 tc lanes; publish approx min d^2 via smem ----
#pragma unroll
    for (int mt = 0; mt < 2; mt++)
#pragma unroll
        for (int h = 0; h < 2; h++) {
            uint32_t k = h2u(kmax[mt][h]);
            k = h2u(__hmax2(u2h(k), u2h(__shfl_xor_sync(0xFFFFFFFFu, k, 1))));
            k = h2u(__hmax2(u2h(k), u2h(__shfl_xor_sync(0xFFFFFFFFu, k, 2))));
            float x2row = __shfl_sync(0xFFFFFFFFu, x2, mt * 16 + h * 8 + g);
            if (tc == 0) {
                __half2 v = u2h(k);
                float smax = fmaxf(__half2float(__low2half(v)), __half2float(__high2half(v)));
                sD2[mbw + mt * 16 + h * 8 + g] = fmaf(smax, -2.f, x2row);
            }
        }
    __syncthreads();

    // ---- fused finalize: thread t owns row t ----
    {
        const int row = blockIdx.x * MT + t;
        float d2a = sD2[t];
        float res = -1.0f;
        if (d2a <= 4.0f) {       // fp16 error << 3.9; rescue: exact fp32 rescan
            const float* xr = x + (size_t)row * D;
            float best = 3.4e38f;
            int   bi = 0;
#pragma unroll 1
            for (int m = 0; m < M; m++) {
                const float* c = codes + (size_t)m * D;
                float s = 0.f;
#pragma unroll 4
                for (int i = 0; i < D; i++) {
                    float dd = __ldg(xr + i) - __ldg(c + i);
                    s = fmaf(dd, dd, s);
                }
                if (s < best) { best = s; bi = m; }
            }
            if (best <= 0.1f) res = (float)bi;
        }
        out[row] = res;
    }
}

extern "C" void kernel_launch(void* const* d_in, const int* in_sizes, int n_in,
                              void* d_out, int out_size) {
    const float* x     = (const float*)d_in[0];
    const float* codes = (const float*)d_in[1];
    float*       out   = (float*)d_out;

    const int M     = in_sizes[1] / D;     // 4096
    const int nRows = in_sizes[0] / D;     // 65536

    prep_kernel<<<(M * 16) / 256, 256>>>(codes, M);
    nn_mma_kernel<<<nRows / MT, TPB>>>(x, codes, out, M);
}

// round 12
// speedup vs baseline: 1.3370x; 1.0162x over previous
#include <cuda_runtime.h>
#include <cuda_fp16.h>
#include <cstdint>

#define D        64
#define MT       128         // x rows per CTA
#define NC       64          // codes per chunk (8KB slot)
#define TPB      160         // 4 consumer warps + 1 producer warp
#define MAXM     4096
#define RING     5

__device__ __align__(16) __half g_codes_f16[MAXM * D];
__device__ __align__(16) __half g_c2h[MAXM];          // fp16(-||c||^2 / 2)

static __device__ __forceinline__ uint32_t su32(const void* p) {
    uint32_t a;
    asm("{ .reg .u64 t; cvta.to.shared.u64 t, %1; cvt.u32.u64 %0, t; }" : "=r"(a) : "l"(p));
    return a;
}
static __device__ __forceinline__ uint32_t h2u(__half2 h) {
    return *reinterpret_cast<uint32_t*>(&h);
}
static __device__ __forceinline__ __half2 u2h(uint32_t u) {
    return *reinterpret_cast<__half2*>(&u);
}

#define LDSM4(r0, r1, r2, r3, addr)                                                   \
    asm volatile("ldmatrix.sync.aligned.m8n8.x4.shared.b16 {%0,%1,%2,%3}, [%4];"      \
                 : "=r"(r0), "=r"(r1), "=r"(r2), "=r"(r3) : "r"(addr))

#define MMA16816H(c0, c1, a, b0, b1)                                                  \
    asm volatile("mma.sync.aligned.m16n8k16.row.col.f16.f16.f16.f16 "                 \
                 "{%0,%1},{%2,%3,%4,%5},{%6,%7},{%0,%1};"                             \
                 : "+r"(c0), "+r"(c1)                                                 \
                 : "r"((a)[0]), "r"((a)[1]), "r"((a)[2]), "r"((a)[3]),                \
                   "r"(b0), "r"(b1))

#define CPASYNC16(saddr, gptr)                                                        \
    asm volatile("cp.async.cg.shared.global [%0], [%1], 16;" :: "r"(saddr), "l"(gptr))
#define CPWAIT0()  asm volatile("cp.async.wait_group 0;")
#define CPASYNC_MBAR_ARRIVE(mbar)                                                     \
    asm volatile("cp.async.mbarrier.arrive.noinc.shared.b64 [%0];" :: "r"(mbar) : "memory")

#define MBARRIER_INIT(mbar, cnt)                                                      \
    asm volatile("mbarrier.init.shared.b64 [%0], %1;" :: "r"(mbar), "r"(cnt) : "memory")
#define MBARRIER_ARRIVE(mbar)                                                         \
    asm volatile("mbarrier.arrive.shared.b64 _, [%0];" :: "r"(mbar) : "memory")

#define MBARRIER_WAIT_PARITY(mbar, parity) do {                                       \
    uint32_t _m = (mbar), _p = (parity), _done;                                       \
    asm volatile("{\n\t.reg .pred p;\n\t"                                             \
        "mbarrier.try_wait.parity.acquire.cta.shared::cta.b64 p, [%1], %2;\n\t"       \
        "selp.b32 %0, 1, 0, p;\n\t}"                                                  \
        : "=r"(_done) : "r"(_m), "r"(_p) : "memory");                                 \
    if (!_done) {                                                                     \
        asm volatile("{\n\t.reg .pred P1;\n\t"                                        \
            "WL_%=:\n\t"                                                              \
            "mbarrier.try_wait.parity.acquire.cta.shared::cta.b64 P1, [%0], %1, 0x989680;\n\t" \
            "@P1 bra.uni WD_%=;\n\t"                                                  \
            "bra.uni WL_%=;\n\t"                                                      \
            "WD_%=:\n\t}" :: "r"(_m), "r"(_p) : "memory");                            \
    }                                                                                 \
} while (0)

// ---------------- prep: 16 threads per code row ----------------
__global__ void prep_kernel(const float* __restrict__ codes, int M) {
    int gid = blockIdx.x * blockDim.x + threadIdx.x;
    int m = gid >> 4, seg = gid & 15;
    if (m >= M) return;
    float4 v = __ldg(reinterpret_cast<const float4*>(codes + (size_t)m * D) + seg);
    float s = v.x * v.x + v.y * v.y + v.z * v.z + v.w * v.w;
    s += __shfl_xor_sync(0xFFFFFFFFu, s, 1);
    s += __shfl_xor_sync(0xFFFFFFFFu, s, 2);
    s += __shfl_xor_sync(0xFFFFFFFFu, s, 4);
    s += __shfl_xor_sync(0xFFFFFFFFu, s, 8);
    uint2 u;
    u.x = h2u(__floats2half2_rn(v.x, v.y));
    u.y = h2u(__floats2half2_rn(v.z, v.w));
    reinterpret_cast<uint2*>(g_codes_f16 + (size_t)m * D)[seg] = u;
    if (seg == 0) g_c2h[m] = __float2half_rn(-0.5f * s);   // acc-init form
}

// dynamic smem layout
#define OFF_RING   0                      // RING x 8192
#define OFF_A      (RING * 8192)          // 16384
#define OFF_FULL   (OFF_A + 16384)        // RING x 8
#define OFF_EMPTY  (OFF_FULL + RING * 8)  // RING x 8
#define OFF_D2     (OFF_EMPTY + RING * 8) // 512
#define SMEM_TOTAL (OFF_D2 + 512)

__global__ void __launch_bounds__(TPB, 3) nn_mma_kernel(
    const float* __restrict__ x, const float* __restrict__ codes,
    float* __restrict__ out, int M)
{
    extern __shared__ __align__(128) unsigned char sm[];
    float* sD2 = reinterpret_cast<float*>(sm + OFF_D2);

    const int t = threadIdx.x;
    const int L = t & 31;
    const int w = t >> 5;
    const int CHUNKS = M / NC;        // 64

    const uint32_t sb = su32(sm);
    const uint32_t ringB  = sb + OFF_RING;
    const uint32_t fullB  = sb + OFF_FULL;
    const uint32_t emptyB = sb + OFF_EMPTY;

    if (t == 0) {
#pragma unroll
        for (int s = 0; s < RING; s++) {
            MBARRIER_INIT(fullB  + s * 8, 32);    // 32 producer lanes arrive-on-complete
            MBARRIER_INIT(emptyB + s * 8, 128);   // 128 consumer threads arrive
        }
    }

    // ---- consumer threads stage x rows into A; x2 in a register ----
    float x2 = 0.f;
    if (t < MT) {
        const float4* xr = reinterpret_cast<const float4*>(
            x + ((size_t)blockIdx.x * MT + t) * D);
        unsigned char* sA = sm + OFF_A;
#pragma unroll
        for (int i = 0; i < 8; i++) {
            float4 f0 = xr[2 * i], f1 = xr[2 * i + 1];
            x2 += f0.x * f0.x + f0.y * f0.y + f0.z * f0.z + f0.w * f0.w;
            x2 += f1.x * f1.x + f1.y * f1.y + f1.z * f1.z + f1.w * f1.w;
            uint4 u;
            u.x = h2u(__floats2half2_rn(f0.x, f0.y));
            u.y = h2u(__floats2half2_rn(f0.z, f0.w));
            u.z = h2u(__floats2half2_rn(f1.x, f1.y));
            u.w = h2u(__floats2half2_rn(f1.z, f1.w));
            *reinterpret_cast<uint4*>(sA + t * 128 + ((i ^ (t & 7)) << 4)) = u;
        }
    }
    __syncthreads();      // A staged + mbarriers initialized

    if (w == 4) {
        // ================= producer warp =================
        int es = 0, ep = 1;       // empty cursor (phase 1: first R waits pass)
#pragma unroll 1
        for (int ch = 0; ch < CHUNKS; ch++) {
            MBARRIER_WAIT_PARITY(emptyB + es * 8, ep);
            const uint32_t dst = ringB + (uint32_t)es * 8192u;
            const char* src = reinterpret_cast<const char*>(g_codes_f16) + (size_t)ch * 8192;
#pragma unroll
            for (int i = 0; i < 16; i++) {
                int idx = L + i * 32;
                int n = idx >> 3, kb = idx & 7;
                CPASYNC16(dst + n * 128 + ((kb ^ (n & 7)) << 4), src + idx * 16);
            }
            CPASYNC_MBAR_ARRIVE(fullB + es * 8);
            if (++es == RING) { es = 0; ep ^= 1; }
        }
        CPWAIT0();
        return;                   // producer done
    }

    // ================= consumer warps (0-3) =================
    // A fragments (registers for whole kernel): warp w owns rows w*32..w*32+31
    uint32_t Af[2][4][4];
    const uint32_t sAb = sb + OFF_A;
    const int mbw = w * 32;
#pragma unroll
    for (int mt = 0; mt < 2; mt++)
#pragma unroll
        for (int k = 0; k < 4; k++) {
            int r  = mbw + mt * 16 + (L & 15);
            int kb = 2 * k + (L >> 4);
            uint32_t addr = sAb + r * 128 + ((kb ^ (r & 7)) << 4);
            LDSM4(Af[mt][k][0], Af[mt][k][1], Af[mt][k][2], Af[mt][k][3], addr);
        }

    const int g   = L >> 2;
    const int tc  = L & 3;
    const int rrb = (L & 7) + ((L >> 4) << 3);
    const int kbb = (L >> 3) & 1;

    __half2 kmax[2][2];
#pragma unroll
    for (int a = 0; a < 2; a++)
#pragma unroll
        for (int b = 0; b < 2; b++) kmax[a][b] = __floats2half2_rn(-65504.f, -65504.f);

    int fs = 0, fp = 0;           // full cursor
#pragma unroll 1
    for (int ch = 0; ch < CHUNKS; ch++) {
        MBARRIER_WAIT_PARITY(fullB + fs * 8, fp);
        const uint32_t sBc = ringB + (uint32_t)fs * 8192u;
        const int cb = ch * NC;

        // c2 for all 8 n-tiles (packed pairs for this lane)
        uint32_t c2[4][2];
#pragma unroll
        for (int p = 0; p < 4; p++) {
            c2[p][0] = __ldg(reinterpret_cast<const uint32_t*>(g_c2h + cb + (2 * p) * 8 + tc * 2));
            c2[p][1] = __ldg(reinterpret_cast<const uint32_t*>(g_c2h + cb + (2 * p + 1) * 8 + tc * 2));
        }

        // 16 independent accumulator chains (p, mt, nt)
        uint32_t acc[4][2][2][2];
#pragma unroll
        for (int p = 0; p < 4; p++)
#pragma unroll
            for (int mt = 0; mt < 2; mt++)
#pragma unroll
                for (int nt = 0; nt < 2; nt++) {
                    acc[p][mt][nt][0] = c2[p][nt];
                    acc[p][mt][nt][1] = c2[p][nt];
                }

#pragma unroll
        for (int k = 0; k < 4; k++) {
            const int kb = 2 * k + kbb;
            uint32_t b[4][4];
#pragma unroll
            for (int p = 0; p < 4; p++) {
                const int rr = p * 16 + rrb;
                LDSM4(b[p][0], b[p][1], b[p][2], b[p][3],
                      sBc + rr * 128 + ((kb ^ (rr & 7)) << 4));
            }
#pragma unroll
            for (int p = 0; p < 4; p++) {
                MMA16816H(acc[p][0][0][0], acc[p][0][0][1], Af[0][k], b[p][0], b[p][1]);
                MMA16816H(acc[p][0][1][0], acc[p][0][1][1], Af[0][k], b[p][2], b[p][3]);
                MMA16816H(acc[p][1][0][0], acc[p][1][0][1], Af[1][k], b[p][0], b[p][1]);
                MMA16816H(acc[p][1][1][0], acc[p][1][1][1], Af[1][k], b[p][2], b[p][3]);
            }
        }

        MBARRIER_ARRIVE(emptyB + fs * 8);    // reads done; slot reusable

#pragma unroll
        for (int p = 0; p < 4; p++)
#pragma unroll
            for (int mt = 0; mt < 2; mt++)
#pragma unroll
                for (int nt = 0; nt < 2; nt++) {
                    kmax[mt][0] = __hmax2(kmax[mt][0], u2h(acc[p][mt][nt][0]));
                    kmax[mt][1] = __hmax2(kmax[mt][1], u2h(acc[p][mt][nt][1]));
                }

        if (++fs == RING) { fs = 0; fp ^= 1; }
    }

    // ---- reduce across 4 tc lanes; publish approx min d^2 ----
#pragma unroll
    for (int mt = 0; mt < 2; mt++)
#pragma unroll
        for (int h = 0; h < 2; h++) {
            uint32_t k = h2u(kmax[mt][h]);
            k = h2u(__hmax2(u2h(k), u2h(__shfl_xor_sync(0xFFFFFFFFu, k, 1))));
            k = h2u(__hmax2(u2h(k), u2h(__shfl_xor_sync(0xFFFFFFFFu, k, 2))));
            float x2row = __shfl_sync(0xFFFFFFFFu, x2, mt * 16 + h * 8 + g);
            if (tc == 0) {
                __half2 v = u2h(k);
                float smax = fmaxf(__half2float(__low2half(v)), __half2float(__high2half(v)));
                sD2[mbw + mt * 16 + h * 8 + g] = fmaf(smax, -2.f, x2row);
            }
        }
    asm volatile("bar.sync 1, 128;" ::: "memory");   // consumer threads only

    // ---- fused finalize: thread t owns row t ----
    {
        const int row = blockIdx.x * MT + t;
        float d2a = sD2[t];
        float res = -1.0f;
        if (d2a <= 4.0f) {       // fp16 error << 3.9; rescue: exact fp32 rescan
            const float* xr = x + (size_t)row * D;
            float best = 3.4e38f;
            int   bi = 0;
#pragma unroll 1
            for (int m = 0; m < M; m++) {
                const float* c = codes + (size_t)m * D;
                float s = 0.f;
#pragma unroll 4
                for (int i = 0; i < D; i++) {
                    float dd = __ldg(xr + i) - __ldg(c + i);
                    s = fmaf(dd, dd, s);
                }
                if (s < best) { best = s; bi = m; }
            }
            if (best <= 0.1f) res = (float)bi;
        }
        out[row] = res;
    }
}

extern "C" void kernel_launch(void* const* d_in, const int* in_sizes, int n_in,
                              void* d_out, int out_size) {
    const float* x     = (const float*)d_in[0];
    const float* codes = (const float*)d_in[1];
    float*       out   = (float*)d_out;

    const int M     = in_sizes[1] / D;     // 4096
    const int nRows = in_sizes[0] / D;     // 65536

    static bool attr = false;
    if (!attr) {
        cudaFuncSetAttribute(nn_mma_kernel,
                             cudaFuncAttributeMaxDynamicSharedMemorySize, SMEM_TOTAL);
        attr = true;
    }

    prep_kernel<<<(M * 16) / 256, 256>>>(codes, M);
    nn_mma_kernel<<<nRows / MT, TPB, SMEM_TOTAL>>>(x, codes, out, M);
}

// round 13
// speedup vs baseline: 1.3448x; 1.0058x over previous
#include <cuda_runtime.h>
#include <cuda_fp16.h>
#include <cstdint>

#define D        64
#define MT       128         // x rows per CTA
#define NC       128         // codes per chunk (16KB slot)
#define TPB      160         // 4 consumer warps + 1 producer warp
#define MAXM     4096
#define RING     2

__device__ __align__(16) __half g_codes_f16[MAXM * D];
__device__ __align__(16) __half g_c2h[MAXM];          // fp16(-||c||^2 / 2)

static __device__ __forceinline__ uint32_t su32(const void* p) {
    uint32_t a;
    asm("{ .reg .u64 t; cvta.to.shared.u64 t, %1; cvt.u32.u64 %0, t; }" : "=r"(a) : "l"(p));
    return a;
}
static __device__ __forceinline__ uint32_t h2u(__half2 h) {
    return *reinterpret_cast<uint32_t*>(&h);
}
static __device__ __forceinline__ __half2 u2h(uint32_t u) {
    return *reinterpret_cast<__half2*>(&u);
}

#define LDSM4(r0, r1, r2, r3, addr)                                                   \
    asm volatile("ldmatrix.sync.aligned.m8n8.x4.shared.b16 {%0,%1,%2,%3}, [%4];"      \
                 : "=r"(r0), "=r"(r1), "=r"(r2), "=r"(r3) : "r"(addr))

#define MMA16816H(c0, c1, a, b0, b1)                                                  \
    asm volatile("mma.sync.aligned.m16n8k16.row.col.f16.f16.f16.f16 "                 \
                 "{%0,%1},{%2,%3,%4,%5},{%6,%7},{%0,%1};"                             \
                 : "+r"(c0), "+r"(c1)                                                 \
                 : "r"((a)[0]), "r"((a)[1]), "r"((a)[2]), "r"((a)[3]),                \
                   "r"(b0), "r"(b1))

#define CPASYNC16(saddr, gptr)                                                        \
    asm volatile("cp.async.cg.shared.global [%0], [%1], 16;" :: "r"(saddr), "l"(gptr))
#define CPWAIT0()  asm volatile("cp.async.wait_group 0;")
#define CPASYNC_MBAR_ARRIVE(mbar)                                                     \
    asm volatile("cp.async.mbarrier.arrive.noinc.shared.b64 [%0];" :: "r"(mbar) : "memory")

#define MBARRIER_INIT(mbar, cnt)                                                      \
    asm volatile("mbarrier.init.shared.b64 [%0], %1;" :: "r"(mbar), "r"(cnt) : "memory")
#define MBARRIER_ARRIVE(mbar)                                                         \
    asm volatile("mbarrier.arrive.shared.b64 _, [%0];" :: "r"(mbar) : "memory")

#define MBARRIER_WAIT_PARITY(mbar, parity) do {                                       \
    uint32_t _m = (mbar), _p = (parity), _done;                                       \
    asm volatile("{\n\t.reg .pred p;\n\t"                                             \
        "mbarrier.try_wait.parity.acquire.cta.shared::cta.b64 p, [%1], %2;\n\t"       \
        "selp.b32 %0, 1, 0, p;\n\t}"                                                  \
        : "=r"(_done) : "r"(_m), "r"(_p) : "memory");                                 \
    if (!_done) {                                                                     \
        asm volatile("{\n\t.reg .pred P1;\n\t"                                        \
            "WL_%=:\n\t"                                                              \
            "mbarrier.try_wait.parity.acquire.cta.shared::cta.b64 P1, [%0], %1, 0x989680;\n\t" \
            "@P1 bra.uni WD_%=;\n\t"                                                  \
            "bra.uni WL_%=;\n\t"                                                      \
            "WD_%=:\n\t}" :: "r"(_m), "r"(_p) : "memory");                            \
    }                                                                                 \
} while (0)

// ---------------- prep: 16 threads per code row ----------------
__global__ void prep_kernel(const float* __restrict__ codes, int M) {
    int gid = blockIdx.x * blockDim.x + threadIdx.x;
    int m = gid >> 4, seg = gid & 15;
    if (m >= M) return;
    float4 v = __ldg(reinterpret_cast<const float4*>(codes + (size_t)m * D) + seg);
    float s = v.x * v.x + v.y * v.y + v.z * v.z + v.w * v.w;
    s += __shfl_xor_sync(0xFFFFFFFFu, s, 1);
    s += __shfl_xor_sync(0xFFFFFFFFu, s, 2);
    s += __shfl_xor_sync(0xFFFFFFFFu, s, 4);
    s += __shfl_xor_sync(0xFFFFFFFFu, s, 8);
    uint2 u;
    u.x = h2u(__floats2half2_rn(v.x, v.y));
    u.y = h2u(__floats2half2_rn(v.z, v.w));
    reinterpret_cast<uint2*>(g_codes_f16 + (size_t)m * D)[seg] = u;
    if (seg == 0) g_c2h[m] = __float2half_rn(-0.5f * s);   // acc-init form
}

// dynamic smem layout
#define OFF_RING   0                       // RING x 16384
#define OFF_A      (RING * 16384)          // 16384
#define OFF_FULL   (OFF_A + 16384)         // RING x 8
#define OFF_EMPTY  (OFF_FULL + RING * 8)   // RING x 8
#define OFF_D2     (OFF_EMPTY + RING * 8)  // 512
#define SMEM_TOTAL (OFF_D2 + 512)

__global__ void __launch_bounds__(TPB, 4) nn_mma_kernel(
    const float* __restrict__ x, const float* __restrict__ codes,
    float* __restrict__ out, int M)
{
    extern __shared__ __align__(128) unsigned char sm[];
    float* sD2 = reinterpret_cast<float*>(sm + OFF_D2);

    const int t = threadIdx.x;
    const int L = t & 31;
    const int w = t >> 5;
    const int CHUNKS = M / NC;        // 32

    const uint32_t sb = su32(sm);
    const uint32_t ringB  = sb + OFF_RING;
    const uint32_t fullB  = sb + OFF_FULL;
    const uint32_t emptyB = sb + OFF_EMPTY;

    if (t == 0) {
#pragma unroll
        for (int s = 0; s < RING; s++) {
            MBARRIER_INIT(fullB  + s * 8, 32);    // 32 producer lanes arrive-on-complete
            MBARRIER_INIT(emptyB + s * 8, 128);   // 128 consumer threads arrive
        }
    }

    // ---- consumer threads stage x rows into A; x2 in a register ----
    float x2 = 0.f;
    if (t < MT) {
        const float4* xr = reinterpret_cast<const float4*>(
            x + ((size_t)blockIdx.x * MT + t) * D);
        unsigned char* sA = sm + OFF_A;
#pragma unroll
        for (int i = 0; i < 8; i++) {
            float4 f0 = xr[2 * i], f1 = xr[2 * i + 1];
            x2 += f0.x * f0.x + f0.y * f0.y + f0.z * f0.z + f0.w * f0.w;
            x2 += f1.x * f1.x + f1.y * f1.y + f1.z * f1.z + f1.w * f1.w;
            uint4 u;
            u.x = h2u(__floats2half2_rn(f0.x, f0.y));
            u.y = h2u(__floats2half2_rn(f0.z, f0.w));
            u.z = h2u(__floats2half2_rn(f1.x, f1.y));
            u.w = h2u(__floats2half2_rn(f1.z, f1.w));
            *reinterpret_cast<uint4*>(sA + t * 128 + ((i ^ (t & 7)) << 4)) = u;
        }
    }
    __syncthreads();      // A staged + mbarriers initialized

    if (w == 4) {
        // ================= producer warp =================
        int es = 0, ep = 1;       // empty cursor (phase 1: first RING waits pass)
#pragma unroll 1
        for (int ch = 0; ch < CHUNKS; ch++) {
            MBARRIER_WAIT_PARITY(emptyB + es * 8, ep);
            const uint32_t dst = ringB + (uint32_t)es * 16384u;
            const char* src = reinterpret_cast<const char*>(g_codes_f16) + (size_t)ch * 16384;
#pragma unroll
            for (int i = 0; i < 32; i++) {
                int idx = L + i * 32;
                int n = idx >> 3, kb = idx & 7;
                CPASYNC16(dst + n * 128 + ((kb ^ (n & 7)) << 4), src + idx * 16);
            }
            CPASYNC_MBAR_ARRIVE(fullB + es * 8);
            if (++es == RING) { es = 0; ep ^= 1; }
        }
        CPWAIT0();
        return;                   // producer done
    }

    // ================= consumer warps (0-3) =================
    uint32_t Af[2][4][4];
    const uint32_t sAb = sb + OFF_A;
    const int mbw = w * 32;
#pragma unroll
    for (int mt = 0; mt < 2; mt++)
#pragma unroll
        for (int k = 0; k < 4; k++) {
            int r  = mbw + mt * 16 + (L & 15);
            int kb = 2 * k + (L >> 4);
            uint32_t addr = sAb + r * 128 + ((kb ^ (r & 7)) << 4);
            LDSM4(Af[mt][k][0], Af[mt][k][1], Af[mt][k][2], Af[mt][k][3], addr);
        }

    const int g   = L >> 2;
    const int tc  = L & 3;
    const int rrb = (L & 7) + ((L >> 4) << 3);
    const int kbb = (L >> 3) & 1;

    __half2 kmax[2][2];
#pragma unroll
    for (int a = 0; a < 2; a++)
#pragma unroll
        for (int b = 0; b < 2; b++) kmax[a][b] = __floats2half2_rn(-65504.f, -65504.f);

    int fs = 0, fp = 0;           // full cursor
#pragma unroll 1
    for (int ch = 0; ch < CHUNKS; ch++) {
        const int cb = ch * NC;

        // ---- hoisted off the critical path: c2 for all 16 n-tiles ----
        uint32_t c2v[8][2];
#pragma unroll
        for (int p = 0; p < 8; p++) {
            c2v[p][0] = __ldg(reinterpret_cast<const uint32_t*>(g_c2h + cb + (2 * p) * 8 + tc * 2));
            c2v[p][1] = __ldg(reinterpret_cast<const uint32_t*>(g_c2h + cb + (2 * p + 1) * 8 + tc * 2));
        }

        MBARRIER_WAIT_PARITY(fullB + fs * 8, fp);
        const uint32_t sBc = ringB + (uint32_t)fs * 16384u;

#pragma unroll
        for (int pp = 0; pp < 4; pp++) {        // p = 2pp, 2pp+1
            // 8 accumulator chains: [pi][mt][nt] x 2 regs
            uint32_t acc[2][2][2][2];
#pragma unroll
            for (int pi = 0; pi < 2; pi++)
#pragma unroll
                for (int mt = 0; mt < 2; mt++)
#pragma unroll
                    for (int nt = 0; nt < 2; nt++) {
                        acc[pi][mt][nt][0] = c2v[2 * pp + pi][nt];
                        acc[pi][mt][nt][1] = c2v[2 * pp + pi][nt];
                    }

            const int r0 = (2 * pp) * 16 + rrb;
            const int r1 = (2 * pp + 1) * 16 + rrb;

            uint32_t f[2][8];
            {
                const int kb = kbb;
                LDSM4(f[0][0], f[0][1], f[0][2], f[0][3], sBc + r0 * 128 + ((kb ^ (r0 & 7)) << 4));
                LDSM4(f[0][4], f[0][5], f[0][6], f[0][7], sBc + r1 * 128 + ((kb ^ (r1 & 7)) << 4));
            }
#pragma unroll
            for (int k = 0; k < 4; k++) {
                if (k < 3) {
                    const int kb = 2 * (k + 1) + kbb;
                    LDSM4(f[(k + 1) & 1][0], f[(k + 1) & 1][1], f[(k + 1) & 1][2], f[(k + 1) & 1][3],
                          sBc + r0 * 128 + ((kb ^ (r0 & 7)) << 4));
                    LDSM4(f[(k + 1) & 1][4], f[(k + 1) & 1][5], f[(k + 1) & 1][6], f[(k + 1) & 1][7],
                          sBc + r1 * 128 + ((kb ^ (r1 & 7)) << 4));
                }
                const uint32_t* b = f[k & 1];
                MMA16816H(acc[0][0][0][0], acc[0][0][0][1], Af[0][k], b[0], b[1]);
                MMA16816H(acc[0][0][1][0], acc[0][0][1][1], Af[0][k], b[2], b[3]);
                MMA16816H(acc[0][1][0][0], acc[0][1][0][1], Af[1][k], b[0], b[1]);
                MMA16816H(acc[0][1][1][0], acc[0][1][1][1], Af[1][k], b[2], b[3]);
                MMA16816H(acc[1][0][0][0], acc[1][0][0][1], Af[0][k], b[4], b[5]);
                MMA16816H(acc[1][0][1][0], acc[1][0][1][1], Af[0][k], b[6], b[7]);
                MMA16816H(acc[1][1][0][0], acc[1][1][0][1], Af[1][k], b[4], b[5]);
                MMA16816H(acc[1][1][1][0], acc[1][1][1][1], Af[1][k], b[6], b[7]);
            }

#pragma unroll
            for (int pi = 0; pi < 2; pi++)
#pragma unroll
                for (int mt = 0; mt < 2; mt++)
#pragma unroll
                    for (int nt = 0; nt < 2; nt++) {
                        kmax[mt][0] = __hmax2(kmax[mt][0], u2h(acc[pi][mt][nt][0]));
                        kmax[mt][1] = __hmax2(kmax[mt][1], u2h(acc[pi][mt][nt][1]));
                    }
        }

        MBARRIER_ARRIVE(emptyB + fs * 8);    // slot reusable
        if (++fs == RING) { fs = 0; fp ^= 1; }
    }

    // ---- reduce across 4 tc lanes; publish approx min d^2 ----
#pragma unroll
    for (int mt = 0; mt < 2; mt++)
#pragma unroll
        for (int h = 0; h < 2; h++) {
            uint32_t k = h2u(kmax[mt][h]);
            k = h2u(__hmax2(u2h(k), u2h(__shfl_xor_sync(0xFFFFFFFFu, k, 1))));
            k = h2u(__hmax2(u2h(k), u2h(__shfl_xor_sync(0xFFFFFFFFu, k, 2))));
            float x2row = __shfl_sync(0xFFFFFFFFu, x2, mt * 16 + h * 8 + g);
            if (tc == 0) {
                __half2 v = u2h(k);
                float smax = fmaxf(__half2float(__low2half(v)), __half2float(__high2half(v)));
                sD2[mbw + mt * 16 + h * 8 + g] = fmaf(smax, -2.f, x2row);
            }
        }
    asm volatile("bar.sync 1, 128;" ::: "memory");   // consumer threads only

    // ---- fused finalize: thread t owns row t ----
    {
        const int row = blockIdx.x * MT + t;
        float d2a = sD2[t];
        float res = -1.0f;
        if (d2a <= 4.0f) {       // fp16 error << 3.9; rescue: exact fp32 rescan
            const float* xr = x + (size_t)row * D;
            float best = 3.4e38f;
            int   bi = 0;
#pragma unroll 1
            for (int m = 0; m < M; m++) {
                const float* c = codes + (size_t)m * D;
                float s = 0.f;
#pragma unroll 4
                for (int i = 0; i < D; i++) {
                    float dd = __ldg(xr + i) - __ldg(c + i);
                    s = fmaf(dd, dd, s);
                }
                if (s < best) { best = s; bi = m; }
            }
            if (best <= 0.1f) res = (float)bi;
        }
        out[row] = res;
    }
}

extern "C" void kernel_launch(void* const* d_in, const int* in_sizes, int n_in,
                              void* d_out, int out_size) {
    const float* x     = (const float*)d_in[0];
    const float* codes = (const float*)d_in[1];
    float*       out   = (float*)d_out;

    const int M     = in_sizes[1] / D;     // 4096
    const int nRows = in_sizes[0] / D;     // 65536

    static bool attr = false;
    if (!attr) {
        cudaFuncSetAttribute(nn_mma_kernel,
                             cudaFuncAttributeMaxDynamicSharedMemorySize, SMEM_TOTAL);
        attr = true;
    }

    prep_kernel<<<(M * 16) / 256, 256>>>(codes, M);
    nn_mma_kernel<<<nRows / MT, TPB, SMEM_TOTAL>>>(x, codes, out, M);
}